// round 3
// baseline (speedup 1.0000x reference)
#include <cuda_runtime.h>
#include <math.h>

#define T_TOK 8192
#define D_DIM 4096
#define KS 4
#define N_SLOTS 128
#define TOPK 1024
#define MAX_ENTRIES 4096   // TOPK * KS worst case into one slot

// ---------------- scratch (static device globals; no allocation) ----------
__device__ float g_importance[T_TOK];
__device__ int   g_slot_cnt[N_SLOTS];
__device__ int   g_slot_tokens[N_SLOTS * MAX_ENTRIES];

// ---------------------------------------------------------------------------
// Kernel 1: per-token importance.
// importance = ||h|| * (1 + entropy/log(Ks)) + sigmoid(h.W + b)
// One block per token row (16KB), 128 threads. Explicit batched float4 loads
// (8 outstanding LDG.128 per thread per half) for high DRAM utilization.
// ---------------------------------------------------------------------------
__global__ void importance_kernel(const float* __restrict__ h,
                                  const float* __restrict__ attn,
                                  const float* __restrict__ W,
                                  const float* __restrict__ b) {
    int t = blockIdx.x;
    const float4* __restrict__ hr = reinterpret_cast<const float4*>(h + (size_t)t * D_DIM);
    const float4* __restrict__ wr = reinterpret_cast<const float4*>(W);

    float hh0 = 0.f, hh1 = 0.f, hw0 = 0.f, hw1 = 0.f;
#pragma unroll
    for (int j = 0; j < 2; j++) {
        float4 ha[4], wa[4];
#pragma unroll
        for (int q = 0; q < 4; q++) ha[q] = hr[threadIdx.x + (j * 4 + q) * 128];
#pragma unroll
        for (int q = 0; q < 4; q++) wa[q] = wr[threadIdx.x + (j * 4 + q) * 128];
#pragma unroll
        for (int q = 0; q < 4; q++) {
            hh0 += ha[q].x * ha[q].x + ha[q].y * ha[q].y;
            hh1 += ha[q].z * ha[q].z + ha[q].w * ha[q].w;
            hw0 += ha[q].x * wa[q].x + ha[q].y * wa[q].y;
            hw1 += ha[q].z * wa[q].z + ha[q].w * wa[q].w;
        }
    }
    float hh = hh0 + hh1, hw = hw0 + hw1;
#pragma unroll
    for (int off = 16; off; off >>= 1) {
        hh += __shfl_xor_sync(0xFFFFFFFFu, hh, off);
        hw += __shfl_xor_sync(0xFFFFFFFFu, hw, off);
    }
    __shared__ float s_hh[4], s_hw[4];
    int wid = threadIdx.x >> 5;
    if ((threadIdx.x & 31) == 0) { s_hh[wid] = hh; s_hw[wid] = hw; }
    __syncthreads();
    if (threadIdx.x == 0) {
        hh = s_hh[0] + s_hh[1] + s_hh[2] + s_hh[3];
        hw = s_hw[0] + s_hw[1] + s_hw[2] + s_hw[3];
        float mag = sqrtf(hh);
        float4 a4 = *reinterpret_cast<const float4*>(attn + t * 4);
        float ent = -(a4.x * logf(a4.x + 1e-8f) + a4.y * logf(a4.y + 1e-8f) +
                      a4.z * logf(a4.z + 1e-8f) + a4.w * logf(a4.w + 1e-8f));
        float surprise = ent * (1.0f / 1.3862943611198906f);   // / log(4)
        float learned = 1.0f / (1.0f + expf(-(hw + b[0])));
        g_importance[t] = mag * (1.0f + surprise) + learned;
    }
}

// ---------------------------------------------------------------------------
// Kernel 2: exact top-1024 selection. Keys live in registers (8 per thread).
// Radix-256 select (4 passes) with ATOMIC-FREE per-warp histograms:
// __match_any_sync groups equal-bin lanes, group leader does a plain
// read-modify-write into the warp-private padded histogram. Bin totals are
// suffix-scanned in parallel (Hillis-Steele). Ties broken toward lowest
// index (matches jax.lax.top_k's selected set). Then builds per-slot lists.
// ---------------------------------------------------------------------------
__global__ void select_kernel(const int* __restrict__ slot_indices) {
    __shared__ int whist[32 * 257];          // per-warp histograms, padded rows
    __shared__ int tot[256];
    __shared__ int s_bucket, s_k, s_cnt;
    __shared__ int s_slot_cnt[N_SLOTS];

    int tid = threadIdx.x;
    int wid = tid >> 5;
    int lane = tid & 31;

    // load keys into registers as order-preserving unsigned
    unsigned int key[8];
#pragma unroll
    for (int i = 0; i < 8; i++) {
        unsigned int u = __float_as_uint(g_importance[tid + i * 1024]);
        u ^= (u & 0x80000000u) ? 0xFFFFFFFFu : 0x80000000u;
        key[i] = u;
    }

    // 4-pass radix select for the TOPK-th largest key value v
    unsigned int prefix = 0, kmask = 0;
    int k = TOPK;
    for (int shift = 24; shift >= 0; shift -= 8) {
        for (int i = tid; i < 32 * 257; i += 1024) whist[i] = 0;
        __syncthreads();

        int* myh = &whist[wid * 257];
#pragma unroll
        for (int i = 0; i < 8; i++) {
            unsigned int u = key[i];
            bool act = ((u & kmask) == prefix);
            unsigned int bin = (u >> shift) & 255u;
            unsigned int tag = act ? bin : 0xFFFFFFFFu;
            unsigned int grp = __match_any_sync(0xFFFFFFFFu, tag);
            int leader = __ffs(grp) - 1;
            if (act && lane == leader) myh[bin] += __popc(grp);
        }
        __syncthreads();

        // total per bin across warps
        if (tid < 256) {
            int s = 0;
#pragma unroll
            for (int w = 0; w < 32; w++) s += whist[w * 257 + tid];
            tot[tid] = s;
        }
        __syncthreads();

        // suffix scan: tot[b] := sum_{bb >= b} count(bb)
        for (int off = 1; off < 256; off <<= 1) {
            int v = 0;
            if (tid < 256) v = tot[tid] + ((tid + off < 256) ? tot[tid + off] : 0);
            __syncthreads();
            if (tid < 256) tot[tid] = v;
            __syncthreads();
        }
        if (tid < 256) {
            int c = tot[tid];
            int cn = (tid < 255) ? tot[tid + 1] : 0;
            if (c >= k && cn < k) { s_bucket = tid; s_k = k - cn; }
        }
        __syncthreads();
        prefix |= ((unsigned int)s_bucket) << shift;
        kmask  |= 0xFFu << shift;
        k = s_k;
        __syncthreads();
    }
    unsigned int v = prefix;
    int r = k;   // need r elements among keys == v, taken at smallest indices

    // count ties (cheap warp-reduce + 32 leader adds)
    if (tid == 0) s_cnt = 0;
    __syncthreads();
    {
        int c = 0;
#pragma unroll
        for (int i = 0; i < 8; i++) c += (key[i] == v);
        c += __shfl_xor_sync(0xFFFFFFFFu, c, 16);
        c += __shfl_xor_sync(0xFFFFFFFFu, c, 8);
        c += __shfl_xor_sync(0xFFFFFFFFu, c, 4);
        c += __shfl_xor_sync(0xFFFFFFFFu, c, 2);
        c += __shfl_xor_sync(0xFFFFFFFFu, c, 1);
        if (lane == 0) atomicAdd(&s_cnt, c);
    }
    __syncthreads();
    int m = s_cnt;

    // index threshold X: smallest X with |{t < X : key==v}| >= r  (rare path)
    int X = T_TOK;
    if (r < m) {
        int lo = 0, hi = T_TOK;
        while (lo < hi) {
            int mid = (lo + hi) >> 1;
            __syncthreads();
            if (tid == 0) s_cnt = 0;
            __syncthreads();
            int c = 0;
#pragma unroll
            for (int i = 0; i < 8; i++) {
                int t = tid + i * 1024;
                c += (t < mid && key[i] == v);
            }
            c += __shfl_xor_sync(0xFFFFFFFFu, c, 16);
            c += __shfl_xor_sync(0xFFFFFFFFu, c, 8);
            c += __shfl_xor_sync(0xFFFFFFFFu, c, 4);
            c += __shfl_xor_sync(0xFFFFFFFFu, c, 2);
            c += __shfl_xor_sync(0xFFFFFFFFu, c, 1);
            if (lane == 0) atomicAdd(&s_cnt, c);
            __syncthreads();
            int got = s_cnt;
            __syncthreads();
            if (got >= r) hi = mid; else lo = mid + 1;
        }
        X = lo;
    }

    // build per-slot token lists
    if (tid < N_SLOTS) s_slot_cnt[tid] = 0;
    __syncthreads();
#pragma unroll
    for (int i = 0; i < 8; i++) {
        int t = tid + i * 1024;
        unsigned int u = key[i];
        if (u > v || (u == v && t < X)) {
            int4 s4 = *reinterpret_cast<const int4*>(slot_indices + t * KS);
            int s;
            s = s4.x; g_slot_tokens[s * MAX_ENTRIES + atomicAdd(&s_slot_cnt[s], 1)] = t;
            s = s4.y; g_slot_tokens[s * MAX_ENTRIES + atomicAdd(&s_slot_cnt[s], 1)] = t;
            s = s4.z; g_slot_tokens[s * MAX_ENTRIES + atomicAdd(&s_slot_cnt[s], 1)] = t;
            s = s4.w; g_slot_tokens[s * MAX_ENTRIES + atomicAdd(&s_slot_cnt[s], 1)] = t;
        }
    }
    __syncthreads();
    if (tid < N_SLOTS) g_slot_cnt[tid] = s_slot_cnt[tid];
}

// ---------------------------------------------------------------------------
// Kernel 3: per-slot gather-sum, mean, EMA write. One block per
// (slot, 512-column chunk). 8-way unrolled over the token list for MLP.
// ---------------------------------------------------------------------------
__global__ void aggregate_kernel(const float* __restrict__ h,
                                 const float* __restrict__ mem,
                                 float* __restrict__ out) {
    int slot = blockIdx.y;
    int col4 = blockIdx.x * 128 + threadIdx.x;   // float4 index (0..1023)
    int cnt = g_slot_cnt[slot];

    const float4* __restrict__ cur_row =
        reinterpret_cast<const float4*>(mem + (size_t)slot * D_DIM);
    float4 cur = cur_row[col4];
    float4 res = cur;

    if (cnt > 0) {
        const int* toks = &g_slot_tokens[slot * MAX_ENTRIES];
        float sx = 0.f, sy = 0.f, sz = 0.f, sw = 0.f;
        int i = 0;
        for (; i + 7 < cnt; i += 8) {
            float4 vv[8];
#pragma unroll
            for (int q = 0; q < 8; q++) {
                int tq = toks[i + q];
                vv[q] = __ldg(&reinterpret_cast<const float4*>(h + (size_t)tq * D_DIM)[col4]);
            }
#pragma unroll
            for (int q = 0; q < 8; q++) {
                sx += vv[q].x; sy += vv[q].y; sz += vv[q].z; sw += vv[q].w;
            }
        }
        for (; i < cnt; i++) {
            int t0 = toks[i];
            float4 v0 = __ldg(&reinterpret_cast<const float4*>(h + (size_t)t0 * D_DIM)[col4]);
            sx += v0.x; sy += v0.y; sz += v0.z; sw += v0.w;
        }
        float inv = 1.0f / (float)cnt;
        res.x = 0.1f * (sx * inv) + 0.9f * cur.x;
        res.y = 0.1f * (sy * inv) + 0.9f * cur.y;
        res.z = 0.1f * (sz * inv) + 0.9f * cur.z;
        res.w = 0.1f * (sw * inv) + 0.9f * cur.w;
    }
    reinterpret_cast<float4*>(out)[slot * (D_DIM / 4) + col4] = res;
}

// ---------------------------------------------------------------------------
extern "C" void kernel_launch(void* const* d_in, const int* in_sizes, int n_in,
                              void* d_out, int out_size) {
    const float* hidden = (const float*)d_in[0];   // [8192, 4096]
    const float* attn   = (const float*)d_in[1];   // [8192, 4]
    const float* memory = (const float*)d_in[2];   // [1, 128, 4096]
    const float* W      = (const float*)d_in[3];   // [1, 4096]
    const float* b      = (const float*)d_in[4];   // [1]
    const int*   slots  = (const int*)d_in[5];     // [8192, 4]
    float* out = (float*)d_out;                    // [1, 128, 4096]

    importance_kernel<<<T_TOK, 128>>>(hidden, attn, W, b);
    select_kernel<<<1, 1024>>>(slots);
    aggregate_kernel<<<dim3(8, N_SLOTS), 128>>>(hidden, memory, out);
}

// round 4
// speedup vs baseline: 1.0862x; 1.0862x over previous
#include <cuda_runtime.h>
#include <math.h>

#define T_TOK 8192
#define D_DIM 4096
#define KS 4
#define N_SLOTS 128
#define TOPK 1024
#define MAX_ENTRIES 4096   // TOPK * KS worst case into one slot
#define TPB_TOK 8          // tokens per importance block

// ---------------- scratch (static device globals; no allocation) ----------
__device__ float g_importance[T_TOK];
__device__ int   g_slot_cnt[N_SLOTS];
__device__ int   g_slot_tokens[N_SLOTS * MAX_ENTRIES];

// ---------------------------------------------------------------------------
// Kernel 1: per-token importance.
// importance = ||h|| * (1 + entropy/log(Ks)) + sigmoid(h.W + b)
// 256 threads/block, 8 tokens/block. W is loaded ONCE per block into
// registers (4 float4/thread) and reused for all 8 tokens, eliminating the
// redundant 128MB of W L2 traffic. Two token rows in flight (8 outstanding
// LDG.128/thread) for memory-level parallelism.
// ---------------------------------------------------------------------------
__global__ void importance_kernel(const float* __restrict__ h,
                                  const float* __restrict__ attn,
                                  const float* __restrict__ W,
                                  const float* __restrict__ b) {
    const int tid = threadIdx.x;             // 0..255
    const int tbase = blockIdx.x * TPB_TOK;
    const float4* __restrict__ wr = reinterpret_cast<const float4*>(W);

    // W resident in registers: thread covers float4 columns tid + q*256
    float4 w[4];
#pragma unroll
    for (int q = 0; q < 4; q++) w[q] = wr[tid + q * 256];

    float ahh[TPB_TOK], ahw[TPB_TOK];

#pragma unroll
    for (int p = 0; p < TPB_TOK; p += 2) {
        const float4* __restrict__ r0 =
            reinterpret_cast<const float4*>(h + (size_t)(tbase + p) * D_DIM);
        const float4* __restrict__ r1 =
            reinterpret_cast<const float4*>(h + (size_t)(tbase + p + 1) * D_DIM);
        float4 a[4], c[4];
#pragma unroll
        for (int q = 0; q < 4; q++) a[q] = r0[tid + q * 256];
#pragma unroll
        for (int q = 0; q < 4; q++) c[q] = r1[tid + q * 256];

        float hh0 = 0.f, hw0 = 0.f, hh1 = 0.f, hw1 = 0.f;
#pragma unroll
        for (int q = 0; q < 4; q++) {
            hh0 += a[q].x * a[q].x + a[q].y * a[q].y + a[q].z * a[q].z + a[q].w * a[q].w;
            hw0 += a[q].x * w[q].x + a[q].y * w[q].y + a[q].z * w[q].z + a[q].w * w[q].w;
            hh1 += c[q].x * c[q].x + c[q].y * c[q].y + c[q].z * c[q].z + c[q].w * c[q].w;
            hw1 += c[q].x * w[q].x + c[q].y * w[q].y + c[q].z * w[q].z + c[q].w * w[q].w;
        }
        ahh[p] = hh0; ahw[p] = hw0; ahh[p + 1] = hh1; ahw[p + 1] = hw1;
    }

    // warp reduce each of the 16 partials, then cross-warp via smem
#pragma unroll
    for (int p = 0; p < TPB_TOK; p++) {
#pragma unroll
        for (int off = 16; off; off >>= 1) {
            ahh[p] += __shfl_xor_sync(0xFFFFFFFFu, ahh[p], off);
            ahw[p] += __shfl_xor_sync(0xFFFFFFFFu, ahw[p], off);
        }
    }
    __shared__ float s_hh[8][TPB_TOK];
    __shared__ float s_hw[8][TPB_TOK];
    const int wid = tid >> 5;
    if ((tid & 31) == 0) {
#pragma unroll
        for (int p = 0; p < TPB_TOK; p++) { s_hh[wid][p] = ahh[p]; s_hw[wid][p] = ahw[p]; }
    }
    __syncthreads();

    if (tid < TPB_TOK) {
        float hh = 0.f, hw = 0.f;
#pragma unroll
        for (int wq = 0; wq < 8; wq++) { hh += s_hh[wq][tid]; hw += s_hw[wq][tid]; }
        int t = tbase + tid;
        float mag = sqrtf(hh);
        float4 a4 = *reinterpret_cast<const float4*>(attn + t * 4);
        float ent = -(a4.x * logf(a4.x + 1e-8f) + a4.y * logf(a4.y + 1e-8f) +
                      a4.z * logf(a4.z + 1e-8f) + a4.w * logf(a4.w + 1e-8f));
        float surprise = ent * (1.0f / 1.3862943611198906f);   // / log(4)
        float learned = 1.0f / (1.0f + expf(-(hw + b[0])));
        g_importance[t] = mag * (1.0f + surprise) + learned;
    }
}

// ---------------------------------------------------------------------------
// Kernel 2: exact top-1024 selection (radix select over sortable uint32,
// ties broken toward lowest index to match jax.lax.top_k's selected SET),
// then build per-slot token lists. Single block, all state block-local,
// so CUDA-graph replays are clean.  (Round-1 version — known 47.7us total.)
// ---------------------------------------------------------------------------
__global__ void select_kernel(const int* __restrict__ slot_indices) {
    __shared__ unsigned int su[T_TOK];   // 32 KB sortable keys
    __shared__ int hist[256];
    __shared__ int s_bucket, s_k, s_cnt;
    __shared__ int s_slot_cnt[N_SLOTS];

    int tid = threadIdx.x;

    // load + convert to order-preserving unsigned keys
#pragma unroll
    for (int i = 0; i < 8; i++) {
        int t = tid + i * 1024;
        unsigned int u = __float_as_uint(g_importance[t]);
        u ^= (u & 0x80000000u) ? 0xFFFFFFFFu : 0x80000000u;
        su[t] = u;
    }
    __syncthreads();

    // 4-pass 8-bit radix select for the value v of the TOPK-th largest key
    unsigned int prefix = 0, kmask = 0;
    int k = TOPK;
    for (int shift = 24; shift >= 0; shift -= 8) {
        if (tid < 256) hist[tid] = 0;
        __syncthreads();
#pragma unroll
        for (int i = 0; i < 8; i++) {
            int t = tid + i * 1024;
            unsigned int u = su[t];
            if ((u & kmask) == prefix) atomicAdd(&hist[(u >> shift) & 255], 1);
        }
        __syncthreads();
        if (tid == 0) {
            int cum = 0, bsel = 0;
            for (int bb = 255; bb >= 0; bb--) {
                cum += hist[bb];
                if (cum >= k) { bsel = bb; s_k = k - (cum - hist[bb]); break; }
            }
            s_bucket = bsel;
        }
        __syncthreads();
        prefix |= ((unsigned int)s_bucket) << shift;
        kmask  |= 0xFFu << shift;
        k = s_k;
        __syncthreads();
    }
    unsigned int v = prefix;
    int r = k;   // need r elements among keys == v, taken at smallest indices

    // count ties
    if (tid == 0) s_cnt = 0;
    __syncthreads();
    {
        int c = 0;
#pragma unroll
        for (int i = 0; i < 8; i++) { int t = tid + i * 1024; c += (su[t] == v); }
        atomicAdd(&s_cnt, c);
    }
    __syncthreads();
    int m = s_cnt;

    // binary search index threshold X: smallest X with |{t < X : key==v}| >= r
    int X = T_TOK;
    if (r < m) {
        int lo = 0, hi = T_TOK;
        while (lo < hi) {
            int mid = (lo + hi) >> 1;
            __syncthreads();
            if (tid == 0) s_cnt = 0;
            __syncthreads();
            int c = 0;
#pragma unroll
            for (int i = 0; i < 8; i++) {
                int t = tid + i * 1024;
                c += (t < mid && su[t] == v);
            }
            atomicAdd(&s_cnt, c);
            __syncthreads();
            int got = s_cnt;
            __syncthreads();
            if (got >= r) hi = mid; else lo = mid + 1;
        }
        X = lo;
    }

    // build per-slot token lists
    if (tid < N_SLOTS) s_slot_cnt[tid] = 0;
    __syncthreads();
#pragma unroll
    for (int i = 0; i < 8; i++) {
        int t = tid + i * 1024;
        unsigned int u = su[t];
        if (u > v || (u == v && t < X)) {
            int4 s4 = *reinterpret_cast<const int4*>(slot_indices + t * KS);
            int s;
            s = s4.x; g_slot_tokens[s * MAX_ENTRIES + atomicAdd(&s_slot_cnt[s], 1)] = t;
            s = s4.y; g_slot_tokens[s * MAX_ENTRIES + atomicAdd(&s_slot_cnt[s], 1)] = t;
            s = s4.z; g_slot_tokens[s * MAX_ENTRIES + atomicAdd(&s_slot_cnt[s], 1)] = t;
            s = s4.w; g_slot_tokens[s * MAX_ENTRIES + atomicAdd(&s_slot_cnt[s], 1)] = t;
        }
    }
    __syncthreads();
    if (tid < N_SLOTS) g_slot_cnt[tid] = s_slot_cnt[tid];
}

// ---------------------------------------------------------------------------
// Kernel 3: per-slot gather-sum, mean, EMA write. One block per
// (slot, 512-col chunk). 4-way unrolled gather. (Round-1 version.)
// ---------------------------------------------------------------------------
__global__ void aggregate_kernel(const float* __restrict__ h,
                                 const float* __restrict__ mem,
                                 float* __restrict__ out) {
    int slot = blockIdx.y;
    int col4 = blockIdx.x * 128 + threadIdx.x;   // float4 index (0..1023)
    int cnt = g_slot_cnt[slot];

    const float4* cur_row = reinterpret_cast<const float4*>(mem + (size_t)slot * D_DIM);
    float4 cur = cur_row[col4];
    float4 res = cur;

    if (cnt > 0) {
        const int* toks = &g_slot_tokens[slot * MAX_ENTRIES];
        float4 a0 = {0, 0, 0, 0}, a1 = {0, 0, 0, 0}, a2 = {0, 0, 0, 0}, a3 = {0, 0, 0, 0};
        int i = 0;
        for (; i + 3 < cnt; i += 4) {
            int t0 = toks[i], t1 = toks[i + 1], t2 = toks[i + 2], t3 = toks[i + 3];
            float4 v0 = reinterpret_cast<const float4*>(h + (size_t)t0 * D_DIM)[col4];
            float4 v1 = reinterpret_cast<const float4*>(h + (size_t)t1 * D_DIM)[col4];
            float4 v2 = reinterpret_cast<const float4*>(h + (size_t)t2 * D_DIM)[col4];
            float4 v3 = reinterpret_cast<const float4*>(h + (size_t)t3 * D_DIM)[col4];
            a0.x += v0.x; a0.y += v0.y; a0.z += v0.z; a0.w += v0.w;
            a1.x += v1.x; a1.y += v1.y; a1.z += v1.z; a1.w += v1.w;
            a2.x += v2.x; a2.y += v2.y; a2.z += v2.z; a2.w += v2.w;
            a3.x += v3.x; a3.y += v3.y; a3.z += v3.z; a3.w += v3.w;
        }
        for (; i < cnt; i++) {
            int t0 = toks[i];
            float4 v0 = reinterpret_cast<const float4*>(h + (size_t)t0 * D_DIM)[col4];
            a0.x += v0.x; a0.y += v0.y; a0.z += v0.z; a0.w += v0.w;
        }
        float inv = 1.0f / (float)cnt;
        float sx = (a0.x + a1.x) + (a2.x + a3.x);
        float sy = (a0.y + a1.y) + (a2.y + a3.y);
        float sz = (a0.z + a1.z) + (a2.z + a3.z);
        float sw = (a0.w + a1.w) + (a2.w + a3.w);
        res.x = 0.1f * (sx * inv) + 0.9f * cur.x;
        res.y = 0.1f * (sy * inv) + 0.9f * cur.y;
        res.z = 0.1f * (sz * inv) + 0.9f * cur.z;
        res.w = 0.1f * (sw * inv) + 0.9f * cur.w;
    }
    reinterpret_cast<float4*>(out)[slot * (D_DIM / 4) + col4] = res;
}

// ---------------------------------------------------------------------------
extern "C" void kernel_launch(void* const* d_in, const int* in_sizes, int n_in,
                              void* d_out, int out_size) {
    const float* hidden = (const float*)d_in[0];   // [8192, 4096]
    const float* attn   = (const float*)d_in[1];   // [8192, 4]
    const float* memory = (const float*)d_in[2];   // [1, 128, 4096]
    const float* W      = (const float*)d_in[3];   // [1, 4096]
    const float* b      = (const float*)d_in[4];   // [1]
    const int*   slots  = (const int*)d_in[5];     // [8192, 4]
    float* out = (float*)d_out;                    // [1, 128, 4096]

    importance_kernel<<<T_TOK / TPB_TOK, 256>>>(hidden, attn, W, b);
    select_kernel<<<1, 1024>>>(slots);
    aggregate_kernel<<<dim3(8, N_SLOTS), 128>>>(hidden, memory, out);
}